// round 6
// baseline (speedup 1.0000x reference)
#include <cuda_runtime.h>
#include <cstdint>

// Problem constants
#define BB 2
#define SS 2048
#define DD 1024
#define HH 16
#define DKK 64
#define MM (BB*SS)      // 4096 rows
#define BHH (BB*HH)     // 32

// Scratch (device globals: allocation-free per harness rules)
__device__ float g_Q[BHH*SS*DKK];     // [b*H+h][s][dk]
__device__ float g_K[BHH*SS*DKK];
__device__ float g_V[BHH*SS*DKK];
__device__ float g_Ctx[MM*DD];        // [b,s, h*dk]

// ---------------------------------------------------------------------------
// tf32 helpers
// ---------------------------------------------------------------------------
__device__ __forceinline__ uint32_t f32_to_tf32(float x) {
    uint32_t r;
    asm("cvt.rna.tf32.f32 %0, %1;" : "=r"(r) : "f"(x));
    return r;
}

__device__ __forceinline__ void mma_tf32(float c[4], const uint32_t a[4], const uint32_t b[2]) {
    asm volatile(
        "mma.sync.aligned.m16n8k8.row.col.f32.tf32.tf32.f32 "
        "{%0,%1,%2,%3}, {%4,%5,%6,%7}, {%8,%9}, {%0,%1,%2,%3};\n"
        : "+f"(c[0]), "+f"(c[1]), "+f"(c[2]), "+f"(c[3])
        : "r"(a[0]), "r"(a[1]), "r"(a[2]), "r"(a[3]), "r"(b[0]), "r"(b[1]));
}

__device__ __forceinline__ void split_store(uint32_t* hi, uint32_t* lo, float x) {
    uint32_t h = f32_to_tf32(x);
    float hf = __uint_as_float(h);
    *hi = h;
    *lo = f32_to_tf32(x - hf);
}

// ---------------------------------------------------------------------------
// Kernel 1: QKV projections as three 4096x1024x1024 GEMMs (tf32x3 mma).
// out[(b*H+h)][s][dk] = sum_d X[b,s,d] * W[h,d,dk]; logical B col n = h*64+dk.
// grid (M/128, D/128, 3), block 256 (8 warps, 2x4 warp grid, 64x32 warp tile)
// ---------------------------------------------------------------------------
__global__ __launch_bounds__(256) void gemm_proj(
    const float* __restrict__ q, const float* __restrict__ kin, const float* __restrict__ v,
    const float* __restrict__ Wq, const float* __restrict__ Wk, const float* __restrict__ Wv)
{
    const int which = blockIdx.z;
    const float* X = (which == 0) ? q : (which == 1) ? kin : v;
    const float* W = (which == 0) ? Wq : (which == 1) ? Wk : Wv;
    float* Out = (which == 0) ? g_Q : (which == 1) ? g_K : g_V;

    const int m0 = blockIdx.x * 128;
    const int n0 = blockIdx.y * 128;
    const int tid = threadIdx.x;
    const int wid = tid >> 5, lane = tid & 31;
    const int wm = wid >> 2, wn = wid & 3;
    const int g = lane >> 2, tg = lane & 3;

    __shared__ uint32_t As_h[128][20], As_l[128][20];
    __shared__ uint32_t Bs_h[128][20], Bs_l[128][20];

    float acc[4][4][4] = {};

    for (int k0 = 0; k0 < DD; k0 += 16) {
        // load A tile [128m x 16k], store m-major
        #pragma unroll
        for (int r = 0; r < 2; r++) {
            int i = tid + r * 256;            // 0..511 float4 slots
            int m = i >> 2, kq = i & 3;
            float4 a4 = *reinterpret_cast<const float4*>(&X[(size_t)(m0 + m) * DD + k0 + kq * 4]);
            split_store(&As_h[m][kq*4+0], &As_l[m][kq*4+0], a4.x);
            split_store(&As_h[m][kq*4+1], &As_l[m][kq*4+1], a4.y);
            split_store(&As_h[m][kq*4+2], &As_l[m][kq*4+2], a4.z);
            split_store(&As_h[m][kq*4+3], &As_l[m][kq*4+3], a4.w);
        }
        // load B tile [16k x 128n] from W[h][d][dk], store n-major
        #pragma unroll
        for (int r = 0; r < 2; r++) {
            int i = tid + r * 256;
            int kk = i >> 5, nq = i & 31;
            int n = nq * 4;
            int gn = n0 + n;
            int h = gn >> 6, dk = gn & 63;
            float4 b4 = *reinterpret_cast<const float4*>(&W[(size_t)h * DD * DKK + (size_t)(k0 + kk) * DKK + dk]);
            split_store(&Bs_h[n+0][kk], &Bs_l[n+0][kk], b4.x);
            split_store(&Bs_h[n+1][kk], &Bs_l[n+1][kk], b4.y);
            split_store(&Bs_h[n+2][kk], &Bs_l[n+2][kk], b4.z);
            split_store(&Bs_h[n+3][kk], &Bs_l[n+3][kk], b4.w);
        }
        __syncthreads();

        #pragma unroll
        for (int kf = 0; kf < 2; kf++) {
            const int kc = kf * 8 + tg;
            uint32_t ah[4][4], al[4][4], bh[4][2], bl[4][2];
            #pragma unroll
            for (int mf = 0; mf < 4; mf++) {
                int mb = wm * 64 + mf * 16;
                ah[mf][0] = As_h[mb+g  ][kc  ]; al[mf][0] = As_l[mb+g  ][kc  ];
                ah[mf][1] = As_h[mb+g+8][kc  ]; al[mf][1] = As_l[mb+g+8][kc  ];
                ah[mf][2] = As_h[mb+g  ][kc+4]; al[mf][2] = As_l[mb+g  ][kc+4];
                ah[mf][3] = As_h[mb+g+8][kc+4]; al[mf][3] = As_l[mb+g+8][kc+4];
            }
            #pragma unroll
            for (int nf = 0; nf < 4; nf++) {
                int nb = wn * 32 + nf * 8;
                bh[nf][0] = Bs_h[nb+g][kc  ]; bl[nf][0] = Bs_l[nb+g][kc  ];
                bh[nf][1] = Bs_h[nb+g][kc+4]; bl[nf][1] = Bs_l[nb+g][kc+4];
            }
            #pragma unroll
            for (int mf = 0; mf < 4; mf++)
                #pragma unroll
                for (int nf = 0; nf < 4; nf++) {
                    mma_tf32(acc[mf][nf], ah[mf], bh[nf]);
                    mma_tf32(acc[mf][nf], ah[mf], bl[nf]);
                    mma_tf32(acc[mf][nf], al[mf], bh[nf]);
                }
        }
        __syncthreads();
    }

    // epilogue: scatter to Out[bh][s][dk]
    #pragma unroll
    for (int mf = 0; mf < 4; mf++) {
        int r0 = m0 + wm * 64 + mf * 16 + g;
        #pragma unroll
        for (int nf = 0; nf < 4; nf++) {
            int c = n0 + wn * 32 + nf * 8 + 2 * tg;
            int h = c >> 6, dk = c & 63;
            {
                int b_ = r0 >> 11, s = r0 & 2047;
                float2 o = make_float2(acc[mf][nf][0], acc[mf][nf][1]);
                *reinterpret_cast<float2*>(&Out[(((size_t)(b_ * HH + h)) * SS + s) * DKK + dk]) = o;
            }
            {
                int r1 = r0 + 8;
                int b_ = r1 >> 11, s = r1 & 2047;
                float2 o = make_float2(acc[mf][nf][2], acc[mf][nf][3]);
                *reinterpret_cast<float2*>(&Out[(((size_t)(b_ * HH + h)) * SS + s) * DKK + dk]) = o;
            }
        }
    }
}

// ---------------------------------------------------------------------------
// Kernel 3: output projection (tf32x3 mma): out[m][n] = sum_c Ctx[m][c]*Wo[n][c] + bo[n]
// grid (M/128, D/128), block 256.
// ---------------------------------------------------------------------------
__global__ __launch_bounds__(256) void gemm_out(
    const float* __restrict__ Wo, const float* __restrict__ bo, float* __restrict__ out)
{
    const int m0 = blockIdx.x * 128;
    const int n0 = blockIdx.y * 128;
    const int tid = threadIdx.x;
    const int wid = tid >> 5, lane = tid & 31;
    const int wm = wid >> 2, wn = wid & 3;
    const int g = lane >> 2, tg = lane & 3;

    __shared__ uint32_t As_h[128][20], As_l[128][20];
    __shared__ uint32_t Bs_h[128][20], Bs_l[128][20];

    float acc[4][4][4] = {};

    for (int k0 = 0; k0 < DD; k0 += 16) {
        #pragma unroll
        for (int r = 0; r < 2; r++) {
            int i = tid + r * 256;
            int m = i >> 2, kq = i & 3;
            float4 a4 = *reinterpret_cast<const float4*>(&g_Ctx[(size_t)(m0 + m) * DD + k0 + kq * 4]);
            split_store(&As_h[m][kq*4+0], &As_l[m][kq*4+0], a4.x);
            split_store(&As_h[m][kq*4+1], &As_l[m][kq*4+1], a4.y);
            split_store(&As_h[m][kq*4+2], &As_l[m][kq*4+2], a4.z);
            split_store(&As_h[m][kq*4+3], &As_l[m][kq*4+3], a4.w);
        }
        #pragma unroll
        for (int r = 0; r < 2; r++) {
            int i = tid + r * 256;
            int n = i >> 2, kq = i & 3;   // B row n of Wo, cols k
            float4 b4 = *reinterpret_cast<const float4*>(&Wo[(size_t)(n0 + n) * DD + k0 + kq * 4]);
            split_store(&Bs_h[n][kq*4+0], &Bs_l[n][kq*4+0], b4.x);
            split_store(&Bs_h[n][kq*4+1], &Bs_l[n][kq*4+1], b4.y);
            split_store(&Bs_h[n][kq*4+2], &Bs_l[n][kq*4+2], b4.z);
            split_store(&Bs_h[n][kq*4+3], &Bs_l[n][kq*4+3], b4.w);
        }
        __syncthreads();

        #pragma unroll
        for (int kf = 0; kf < 2; kf++) {
            const int kc = kf * 8 + tg;
            uint32_t ah[4][4], al[4][4], bh[4][2], bl[4][2];
            #pragma unroll
            for (int mf = 0; mf < 4; mf++) {
                int mb = wm * 64 + mf * 16;
                ah[mf][0] = As_h[mb+g  ][kc  ]; al[mf][0] = As_l[mb+g  ][kc  ];
                ah[mf][1] = As_h[mb+g+8][kc  ]; al[mf][1] = As_l[mb+g+8][kc  ];
                ah[mf][2] = As_h[mb+g  ][kc+4]; al[mf][2] = As_l[mb+g  ][kc+4];
                ah[mf][3] = As_h[mb+g+8][kc+4]; al[mf][3] = As_l[mb+g+8][kc+4];
            }
            #pragma unroll
            for (int nf = 0; nf < 4; nf++) {
                int nb = wn * 32 + nf * 8;
                bh[nf][0] = Bs_h[nb+g][kc  ]; bl[nf][0] = Bs_l[nb+g][kc  ];
                bh[nf][1] = Bs_h[nb+g][kc+4]; bl[nf][1] = Bs_l[nb+g][kc+4];
            }
            #pragma unroll
            for (int mf = 0; mf < 4; mf++)
                #pragma unroll
                for (int nf = 0; nf < 4; nf++) {
                    mma_tf32(acc[mf][nf], ah[mf], bh[nf]);
                    mma_tf32(acc[mf][nf], ah[mf], bl[nf]);
                    mma_tf32(acc[mf][nf], al[mf], bh[nf]);
                }
        }
        __syncthreads();
    }

    #pragma unroll
    for (int mf = 0; mf < 4; mf++) {
        int r0 = m0 + wm * 64 + mf * 16 + g;
        #pragma unroll
        for (int nf = 0; nf < 4; nf++) {
            int c = n0 + wn * 32 + nf * 8 + 2 * tg;
            float2 bb = *reinterpret_cast<const float2*>(&bo[c]);
            float2 o0 = make_float2(acc[mf][nf][0] + bb.x, acc[mf][nf][1] + bb.y);
            float2 o1 = make_float2(acc[mf][nf][2] + bb.x, acc[mf][nf][3] + bb.y);
            *reinterpret_cast<float2*>(&out[(size_t)r0 * DD + c]) = o0;
            *reinterpret_cast<float2*>(&out[(size_t)(r0 + 8) * DD + c]) = o1;
        }
    }
}

// ---------------------------------------------------------------------------
// Kernel 2: causal flash attention (unchanged from passing R2 version).
// grid: (S/64, B*H), block 256.
// ---------------------------------------------------------------------------
__global__ __launch_bounds__(256) void attn_kernel()
{
    extern __shared__ float sm[];
    float (*Qs)[65] = (float(*)[65])(sm);                 // Qs[k][r]
    float (*Ks)[65] = (float(*)[65])(sm + 64 * 65);       // Ks[k][c]
    float (*Ps)[65] = (float(*)[65])(sm + 2 * 64 * 65);   // Ps[t][r]
    float (*Vs)[64] = (float(*)[64])(sm + 3 * 64 * 65);   // Vs[t][c]

    const int bh = blockIdx.y;
    const int qi = (gridDim.x - 1) - blockIdx.x;          // heavy tiles first
    const int i0 = qi * 64;
    const float* Qg = g_Q + (size_t)bh * SS * DKK;
    const float* Kg = g_K + (size_t)bh * SS * DKK;
    const float* Vg = g_V + (size_t)bh * SS * DKK;

    const int tid = threadIdx.x;
    const int tx = tid & 15, ty = tid >> 4;

    #pragma unroll
    for (int rep = 0; rep < 4; rep++) {
        int idx = tid + rep * 256;
        int r = idx >> 4, c4 = idx & 15;
        float4 a4 = *reinterpret_cast<const float4*>(&Qg[(i0 + r) * DKK + c4 * 4]);
        Qs[c4*4+0][r] = a4.x; Qs[c4*4+1][r] = a4.y;
        Qs[c4*4+2][r] = a4.z; Qs[c4*4+3][r] = a4.w;
    }

    float acc[4][4] = {};
    float mrow[4], lsum[4];
    #pragma unroll
    for (int i = 0; i < 4; i++) { mrow[i] = -1e30f; lsum[i] = 0.f; }
    const float scale = 0.125f;

    const int ntiles = qi + 1;
    for (int j = 0; j < ntiles; j++) {
        const int j0 = j * 64;
        __syncthreads();
        #pragma unroll
        for (int rep = 0; rep < 4; rep++) {
            int idx = tid + rep * 256;
            int r = idx >> 4, c4 = idx & 15;
            float4 a4 = *reinterpret_cast<const float4*>(&Kg[(j0 + r) * DKK + c4 * 4]);
            Ks[c4*4+0][r] = a4.x; Ks[c4*4+1][r] = a4.y;
            Ks[c4*4+2][r] = a4.z; Ks[c4*4+3][r] = a4.w;
        }
        #pragma unroll
        for (int rep = 0; rep < 4; rep++) {
            int idx = tid + rep * 256;
            int t = idx >> 4, c4 = idx & 15;
            *reinterpret_cast<float4*>(&Vs[t][c4 * 4]) =
                *reinterpret_cast<const float4*>(&Vg[(j0 + t) * DKK + c4 * 4]);
        }
        __syncthreads();

        float sc[4][4] = {};
        #pragma unroll 16
        for (int kk = 0; kk < 64; kk++) {
            float a[4], b[4];
            #pragma unroll
            for (int i = 0; i < 4; i++) a[i] = Qs[kk][ty * 4 + i];
            #pragma unroll
            for (int jj = 0; jj < 4; jj++) b[jj] = Ks[kk][tx * 4 + jj];
            #pragma unroll
            for (int i = 0; i < 4; i++)
                #pragma unroll
                for (int jj = 0; jj < 4; jj++)
                    sc[i][jj] += a[i] * b[jj];
        }

        const bool diag = (j == qi);
        float rmax[4];
        #pragma unroll
        for (int i = 0; i < 4; i++) {
            rmax[i] = -1e30f;
            #pragma unroll
            for (int jj = 0; jj < 4; jj++) {
                float s_ = sc[i][jj] * scale;
                if (diag && (j0 + tx * 4 + jj) > (i0 + ty * 4 + i)) s_ = -1e30f;
                sc[i][jj] = s_;
                rmax[i] = fmaxf(rmax[i], s_);
            }
        }
        #pragma unroll
        for (int off = 8; off > 0; off >>= 1)
            #pragma unroll
            for (int i = 0; i < 4; i++)
                rmax[i] = fmaxf(rmax[i], __shfl_xor_sync(0xffffffffu, rmax[i], off));

        #pragma unroll
        for (int i = 0; i < 4; i++) {
            float mnew = fmaxf(mrow[i], rmax[i]);
            float corr = __expf(mrow[i] - mnew);
            mrow[i] = mnew;
            float rs = 0.f;
            #pragma unroll
            for (int jj = 0; jj < 4; jj++) {
                float p = __expf(sc[i][jj] - mnew);
                sc[i][jj] = p;
                rs += p;
            }
            #pragma unroll
            for (int off = 8; off > 0; off >>= 1)
                rs += __shfl_xor_sync(0xffffffffu, rs, off);
            lsum[i] = lsum[i] * corr + rs;
            #pragma unroll
            for (int c = 0; c < 4; c++) acc[i][c] *= corr;
        }

        #pragma unroll
        for (int i = 0; i < 4; i++)
            #pragma unroll
            for (int jj = 0; jj < 4; jj++)
                Ps[tx * 4 + jj][ty * 4 + i] = sc[i][jj];
        __syncthreads();

        #pragma unroll 16
        for (int kk = 0; kk < 64; kk++) {
            float a[4], b[4];
            #pragma unroll
            for (int i = 0; i < 4; i++) a[i] = Ps[kk][ty * 4 + i];
            #pragma unroll
            for (int jj = 0; jj < 4; jj++) b[jj] = Vs[kk][tx * 4 + jj];
            #pragma unroll
            for (int i = 0; i < 4; i++)
                #pragma unroll
                for (int jj = 0; jj < 4; jj++)
                    acc[i][jj] += a[i] * b[jj];
        }
    }

    const int b_ = bh / HH, h = bh % HH;
    #pragma unroll
    for (int i = 0; i < 4; i++) {
        float inv = 1.f / lsum[i];
        int s = i0 + ty * 4 + i;
        float* orow = &g_Ctx[((size_t)(b_ * SS + s)) * DD + h * DKK];
        float4 o4 = make_float4(acc[i][0] * inv, acc[i][1] * inv,
                                acc[i][2] * inv, acc[i][3] * inv);
        *reinterpret_cast<float4*>(orow + tx * 4) = o4;
    }
}

// ---------------------------------------------------------------------------
extern "C" void kernel_launch(void* const* d_in, const int* in_sizes, int n_in,
                              void* d_out, int out_size)
{
    const float* q  = (const float*)d_in[0];
    const float* k  = (const float*)d_in[1];
    const float* v  = (const float*)d_in[2];
    const float* Wq = (const float*)d_in[3];
    const float* Wk = (const float*)d_in[4];
    const float* Wv = (const float*)d_in[5];
    const float* Wo = (const float*)d_in[6];
    const float* bo = (const float*)d_in[7];
    float* out = (float*)d_out;

    gemm_proj<<<dim3(MM / 128, DD / 128, 3), 256>>>(q, k, v, Wq, Wk, Wv);

    int smem_bytes = (3 * 64 * 65 + 64 * 64) * (int)sizeof(float);   // ~66 KB
    cudaFuncSetAttribute(attn_kernel, cudaFuncAttributeMaxDynamicSharedMemorySize, smem_bytes);
    attn_kernel<<<dim3(SS / 64, BHH), 256, smem_bytes>>>();

    gemm_out<<<dim3(MM / 128, DD / 128), 256>>>(Wo, bo, out);
}

// round 9
// speedup vs baseline: 1.1690x; 1.1690x over previous
#include <cuda_runtime.h>
#include <cuda_bf16.h>
#include <cstdint>

// Problem constants
#define BB 2
#define SS 2048
#define DD 1024
#define HH 16
#define DKK 64
#define MM (BB*SS)      // 4096
#define BHH (BB*HH)     // 32

// Scratch (device globals: allocation-free per harness rules)
__device__ float g_Q[BHH*SS*DKK];
__device__ float g_K[BHH*SS*DKK];
__device__ float g_V[BHH*SS*DKK];
__device__ float g_Ctx[MM*DD];

// ---------------------------------------------------------------------------
// bf16 helpers
// ---------------------------------------------------------------------------
__device__ __forceinline__ void mma_bf16(float c[4], const uint32_t a[4], const uint32_t b[2]) {
    asm volatile(
        "mma.sync.aligned.m16n8k16.row.col.f32.bf16.bf16.f32 "
        "{%0,%1,%2,%3}, {%4,%5,%6,%7}, {%8,%9}, {%0,%1,%2,%3};\n"
        : "+f"(c[0]), "+f"(c[1]), "+f"(c[2]), "+f"(c[3])
        : "r"(a[0]), "r"(a[1]), "r"(a[2]), "r"(a[3]), "r"(b[0]), "r"(b[1]));
}

// split two floats into packed bf16 hi-pair and lo-pair (exact residual split)
__device__ __forceinline__ void split2(float x0, float x1, uint32_t& hi, uint32_t& lo) {
    __nv_bfloat16 h0 = __float2bfloat16(x0);
    __nv_bfloat16 h1 = __float2bfloat16(x1);
    __nv_bfloat16 l0 = __float2bfloat16(x0 - __bfloat162float(h0));
    __nv_bfloat16 l1 = __float2bfloat16(x1 - __bfloat162float(h1));
    hi = (uint32_t)__bfloat16_as_ushort(h0) | ((uint32_t)__bfloat16_as_ushort(h1) << 16);
    lo = (uint32_t)__bfloat16_as_ushort(l0) | ((uint32_t)__bfloat16_as_ushort(l1) << 16);
}

// ---------------------------------------------------------------------------
// Kernel 1: QKV projections, bf16x3 HMMA, software-prefetch pipeline.
// C[m, n=h*64+dk] = sum_d X[m,d] * W[h,d,dk]
// grid (32, 8, 3), block 256 (8 warps, 2x4 warp grid, 64x32 warp tiles), BK=32.
// Smem: packed bf16-pair planes [128 rows][20 kpairs] (16 used + 4 pad).
// ---------------------------------------------------------------------------
__global__ __launch_bounds__(256) void gemm_proj_bf16(
    const float* __restrict__ q, const float* __restrict__ kin, const float* __restrict__ v,
    const float* __restrict__ Wq, const float* __restrict__ Wk, const float* __restrict__ Wv)
{
    __shared__ uint32_t As_h[128][20], As_l[128][20];
    __shared__ uint32_t Bs_h[128][20], Bs_l[128][20];

    const int which = blockIdx.z;
    const float* X = (which == 0) ? q : (which == 1) ? kin : v;
    const float* W = (which == 0) ? Wq : (which == 1) ? Wk : Wv;
    float* Out = (which == 0) ? g_Q : (which == 1) ? g_K : g_V;

    const int m0 = blockIdx.x * 128;
    const int n0 = blockIdx.y * 128;
    const int tid = threadIdx.x;
    const int wid = tid >> 5, lane = tid & 31;
    const int wm = wid >> 2, wn = wid & 3;
    const int g = lane >> 2, tg = lane & 3;

    float acc[4][4][4] = {};
    float4 pa[4], pb[4];

    // prefetch stage 0
    #pragma unroll
    for (int r = 0; r < 4; r++) {
        int i = tid + r * 256;
        int am = i >> 3, aq = i & 7;
        pa[r] = *reinterpret_cast<const float4*>(&X[(size_t)(m0 + am) * DD + aq * 4]);
    }
    #pragma unroll
    for (int r = 0; r < 4; r++) {
        int i = tid + r * 256;
        int kk = i >> 5, nq = i & 31;
        int gn = n0 + nq * 4, h = gn >> 6, dk = gn & 63;
        pb[r] = *reinterpret_cast<const float4*>(&W[(size_t)h * DD * DKK + (size_t)kk * DKK + dk]);
    }

    for (int s = 0; s < 32; s++) {
        // convert + store A (pairs along k)
        #pragma unroll
        for (int r = 0; r < 4; r++) {
            int i = tid + r * 256;
            int am = i >> 3, aq = i & 7;
            uint32_t h0, l0, h1, l1;
            split2(pa[r].x, pa[r].y, h0, l0);
            split2(pa[r].z, pa[r].w, h1, l1);
            As_h[am][aq*2  ] = h0; As_l[am][aq*2  ] = l0;
            As_h[am][aq*2+1] = h1; As_l[am][aq*2+1] = l1;
        }
        // convert + store B (scalar scatter: 4 n's at one k)
        #pragma unroll
        for (int r = 0; r < 4; r++) {
            int i = tid + r * 256;
            int kk = i >> 5, nq = i & 31;
            float xs[4] = {pb[r].x, pb[r].y, pb[r].z, pb[r].w};
            #pragma unroll
            for (int e = 0; e < 4; e++) {
                int nn = nq * 4 + e;
                __nv_bfloat16 h = __float2bfloat16(xs[e]);
                __nv_bfloat16 l = __float2bfloat16(xs[e] - __bfloat162float(h));
                reinterpret_cast<__nv_bfloat16*>(&Bs_h[nn][kk >> 1])[kk & 1] = h;
                reinterpret_cast<__nv_bfloat16*>(&Bs_l[nn][kk >> 1])[kk & 1] = l;
            }
        }
        __syncthreads();

        // prefetch next stage while computing this one
        if (s + 1 < 32) {
            const int k0 = (s + 1) * 32;
            #pragma unroll
            for (int r = 0; r < 4; r++) {
                int i = tid + r * 256;
                int am = i >> 3, aq = i & 7;
                pa[r] = *reinterpret_cast<const float4*>(&X[(size_t)(m0 + am) * DD + k0 + aq * 4]);
            }
            #pragma unroll
            for (int r = 0; r < 4; r++) {
                int i = tid + r * 256;
                int kk = i >> 5, nq = i & 31;
                int gn = n0 + nq * 4, h = gn >> 6, dk = gn & 63;
                pb[r] = *reinterpret_cast<const float4*>(&W[(size_t)h * DD * DKK + (size_t)(k0 + kk) * DKK + dk]);
            }
        }

        // compute: 2 k16 steps
        #pragma unroll
        for (int kf = 0; kf < 2; kf++) {
            const int kb = kf * 8;
            uint32_t bh[4][2], bl[4][2];
            #pragma unroll
            for (int nf = 0; nf < 4; nf++) {
                int nb = wn * 32 + nf * 8;
                bh[nf][0] = Bs_h[nb+g][kb+tg]; bh[nf][1] = Bs_h[nb+g][kb+tg+4];
                bl[nf][0] = Bs_l[nb+g][kb+tg]; bl[nf][1] = Bs_l[nb+g][kb+tg+4];
            }
            #pragma unroll
            for (int mf = 0; mf < 4; mf++) {
                int mb = wm * 64 + mf * 16;
                uint32_t ah[4], al[4];
                ah[0] = As_h[mb+g  ][kb+tg  ]; al[0] = As_l[mb+g  ][kb+tg  ];
                ah[1] = As_h[mb+g+8][kb+tg  ]; al[1] = As_l[mb+g+8][kb+tg  ];
                ah[2] = As_h[mb+g  ][kb+tg+4]; al[2] = As_l[mb+g  ][kb+tg+4];
                ah[3] = As_h[mb+g+8][kb+tg+4]; al[3] = As_l[mb+g+8][kb+tg+4];
                #pragma unroll
                for (int nf = 0; nf < 4; nf++) {
                    mma_bf16(acc[mf][nf], ah, bh[nf]);
                    mma_bf16(acc[mf][nf], ah, bl[nf]);
                    mma_bf16(acc[mf][nf], al, bh[nf]);
                }
            }
        }
        __syncthreads();
    }

    // epilogue: scatter to Out[bh][s][dk] (same mapping as validated R6 kernel)
    #pragma unroll
    for (int mf = 0; mf < 4; mf++) {
        int r0 = m0 + wm * 64 + mf * 16 + g;
        #pragma unroll
        for (int nf = 0; nf < 4; nf++) {
            int c = n0 + wn * 32 + nf * 8 + 2 * tg;
            int h = c >> 6, dk = c & 63;
            {
                int b_ = r0 >> 11, sI = r0 & 2047;
                float2 o = make_float2(acc[mf][nf][0], acc[mf][nf][1]);
                *reinterpret_cast<float2*>(&Out[(((size_t)(b_ * HH + h)) * SS + sI) * DKK + dk]) = o;
            }
            {
                int r1 = r0 + 8;
                int b_ = r1 >> 11, sI = r1 & 2047;
                float2 o = make_float2(acc[mf][nf][2], acc[mf][nf][3]);
                *reinterpret_cast<float2*>(&Out[(((size_t)(b_ * HH + h)) * SS + sI) * DKK + dk]) = o;
            }
        }
    }
}

// ---------------------------------------------------------------------------
// Kernel 3: output projection, bf16x3 HMMA, same pipeline.
// out[m][n] = sum_c Ctx[m][c] * Wo[n][c] + bo[n].  grid (32, 8), block 256.
// Both A (Ctx) and B (Wo) are row-major along k -> same loader shape.
// ---------------------------------------------------------------------------
__global__ __launch_bounds__(256) void gemm_out_bf16(
    const float* __restrict__ Wo, const float* __restrict__ bo, float* __restrict__ out)
{
    __shared__ uint32_t As_h[128][20], As_l[128][20];
    __shared__ uint32_t Bs_h[128][20], Bs_l[128][20];

    const int m0 = blockIdx.x * 128;
    const int n0 = blockIdx.y * 128;
    const int tid = threadIdx.x;
    const int wid = tid >> 5, lane = tid & 31;
    const int wm = wid >> 2, wn = wid & 3;
    const int g = lane >> 2, tg = lane & 3;

    float acc[4][4][4] = {};
    float4 pa[4], pb[4];

    #pragma unroll
    for (int r = 0; r < 4; r++) {
        int i = tid + r * 256;
        int am = i >> 3, aq = i & 7;
        pa[r] = *reinterpret_cast<const float4*>(&g_Ctx[(size_t)(m0 + am) * DD + aq * 4]);
        pb[r] = *reinterpret_cast<const float4*>(&Wo[(size_t)(n0 + am) * DD + aq * 4]);
    }

    for (int s = 0; s < 32; s++) {
        #pragma unroll
        for (int r = 0; r < 4; r++) {
            int i = tid + r * 256;
            int am = i >> 3, aq = i & 7;
            uint32_t h0, l0, h1, l1;
            split2(pa[r].x, pa[r].y, h0, l0);
            split2(pa[r].z, pa[r].w, h1, l1);
            As_h[am][aq*2  ] = h0; As_l[am][aq*2  ] = l0;
            As_h[am][aq*2+1] = h1; As_l[am][aq*2+1] = l1;
            split2(pb[r].x, pb[r].y, h0, l0);
            split2(pb[r].z, pb[r].w, h1, l1);
            Bs_h[am][aq*2  ] = h0; Bs_l[am][aq*2  ] = l0;
            Bs_h[am][aq*2+1] = h1; Bs_l[am][aq*2+1] = l1;
        }
        __syncthreads();

        if (s + 1 < 32) {
            const int k0 = (s + 1) * 32;
            #pragma unroll
            for (int r = 0; r < 4; r++) {
                int i = tid + r * 256;
                int am = i >> 3, aq = i & 7;
                pa[r] = *reinterpret_cast<const float4*>(&g_Ctx[(size_t)(m0 + am) * DD + k0 + aq * 4]);
                pb[r] = *reinterpret_cast<const float4*>(&Wo[(size_t)(n0 + am) * DD + k0 + aq * 4]);
            }
        }

        #pragma unroll
        for (int kf = 0; kf < 2; kf++) {
            const int kb = kf * 8;
            uint32_t bh[4][2], bl[4][2];
            #pragma unroll
            for (int nf = 0; nf < 4; nf++) {
                int nb = wn * 32 + nf * 8;
                bh[nf][0] = Bs_h[nb+g][kb+tg]; bh[nf][1] = Bs_h[nb+g][kb+tg+4];
                bl[nf][0] = Bs_l[nb+g][kb+tg]; bl[nf][1] = Bs_l[nb+g][kb+tg+4];
            }
            #pragma unroll
            for (int mf = 0; mf < 4; mf++) {
                int mb = wm * 64 + mf * 16;
                uint32_t ah[4], al[4];
                ah[0] = As_h[mb+g  ][kb+tg  ]; al[0] = As_l[mb+g  ][kb+tg  ];
                ah[1] = As_h[mb+g+8][kb+tg  ]; al[1] = As_l[mb+g+8][kb+tg  ];
                ah[2] = As_h[mb+g  ][kb+tg+4]; al[2] = As_l[mb+g  ][kb+tg+4];
                ah[3] = As_h[mb+g+8][kb+tg+4]; al[3] = As_l[mb+g+8][kb+tg+4];
                #pragma unroll
                for (int nf = 0; nf < 4; nf++) {
                    mma_bf16(acc[mf][nf], ah, bh[nf]);
                    mma_bf16(acc[mf][nf], ah, bl[nf]);
                    mma_bf16(acc[mf][nf], al, bh[nf]);
                }
            }
        }
        __syncthreads();
    }

    #pragma unroll
    for (int mf = 0; mf < 4; mf++) {
        int r0 = m0 + wm * 64 + mf * 16 + g;
        #pragma unroll
        for (int nf = 0; nf < 4; nf++) {
            int c = n0 + wn * 32 + nf * 8 + 2 * tg;
            float2 bb = *reinterpret_cast<const float2*>(&bo[c]);
            float2 o0 = make_float2(acc[mf][nf][0] + bb.x, acc[mf][nf][1] + bb.y);
            float2 o1 = make_float2(acc[mf][nf][2] + bb.x, acc[mf][nf][3] + bb.y);
            *reinterpret_cast<float2*>(&out[(size_t)r0 * DD + c]) = o0;
            *reinterpret_cast<float2*>(&out[(size_t)(r0 + 8) * DD + c]) = o1;
        }
    }
}

// ---------------------------------------------------------------------------
// Kernel 2: causal flash attention (unchanged, known-good R2 version).
// grid: (S/64, B*H), block 256.
// ---------------------------------------------------------------------------
__global__ __launch_bounds__(256) void attn_kernel()
{
    extern __shared__ float sm[];
    float (*Qs)[65] = (float(*)[65])(sm);
    float (*Ks)[65] = (float(*)[65])(sm + 64 * 65);
    float (*Ps)[65] = (float(*)[65])(sm + 2 * 64 * 65);
    float (*Vs)[64] = (float(*)[64])(sm + 3 * 64 * 65);

    const int bh = blockIdx.y;
    const int qi = (gridDim.x - 1) - blockIdx.x;
    const int i0 = qi * 64;
    const float* Qg = g_Q + (size_t)bh * SS * DKK;
    const float* Kg = g_K + (size_t)bh * SS * DKK;
    const float* Vg = g_V + (size_t)bh * SS * DKK;

    const int tid = threadIdx.x;
    const int tx = tid & 15, ty = tid >> 4;

    #pragma unroll
    for (int rep = 0; rep < 4; rep++) {
        int idx = tid + rep * 256;
        int r = idx >> 4, c4 = idx & 15;
        float4 a4 = *reinterpret_cast<const float4*>(&Qg[(i0 + r) * DKK + c4 * 4]);
        Qs[c4*4+0][r] = a4.x; Qs[c4*4+1][r] = a4.y;
        Qs[c4*4+2][r] = a4.z; Qs[c4*4+3][r] = a4.w;
    }

    float acc[4][4] = {};
    float mrow[4], lsum[4];
    #pragma unroll
    for (int i = 0; i < 4; i++) { mrow[i] = -1e30f; lsum[i] = 0.f; }
    const float scale = 0.125f;

    const int ntiles = qi + 1;
    for (int j = 0; j < ntiles; j++) {
        const int j0 = j * 64;
        __syncthreads();
        #pragma unroll
        for (int rep = 0; rep < 4; rep++) {
            int idx = tid + rep * 256;
            int r = idx >> 4, c4 = idx & 15;
            float4 a4 = *reinterpret_cast<const float4*>(&Kg[(j0 + r) * DKK + c4 * 4]);
            Ks[c4*4+0][r] = a4.x; Ks[c4*4+1][r] = a4.y;
            Ks[c4*4+2][r] = a4.z; Ks[c4*4+3][r] = a4.w;
        }
        #pragma unroll
        for (int rep = 0; rep < 4; rep++) {
            int idx = tid + rep * 256;
            int t = idx >> 4, c4 = idx & 15;
            *reinterpret_cast<float4*>(&Vs[t][c4 * 4]) =
                *reinterpret_cast<const float4*>(&Vg[(j0 + t) * DKK + c4 * 4]);
        }
        __syncthreads();

        float sc[4][4] = {};
        #pragma unroll 16
        for (int kk = 0; kk < 64; kk++) {
            float a[4], b[4];
            #pragma unroll
            for (int i = 0; i < 4; i++) a[i] = Qs[kk][ty * 4 + i];
            #pragma unroll
            for (int jj = 0; jj < 4; jj++) b[jj] = Ks[kk][tx * 4 + jj];
            #pragma unroll
            for (int i = 0; i < 4; i++)
                #pragma unroll
                for (int jj = 0; jj < 4; jj++)
                    sc[i][jj] += a[i] * b[jj];
        }

        const bool diag = (j == qi);
        float rmax[4];
        #pragma unroll
        for (int i = 0; i < 4; i++) {
            rmax[i] = -1e30f;
            #pragma unroll
            for (int jj = 0; jj < 4; jj++) {
                float s_ = sc[i][jj] * scale;
                if (diag && (j0 + tx * 4 + jj) > (i0 + ty * 4 + i)) s_ = -1e30f;
                sc[i][jj] = s_;
                rmax[i] = fmaxf(rmax[i], s_);
            }
        }
        #pragma unroll
        for (int off = 8; off > 0; off >>= 1)
            #pragma unroll
            for (int i = 0; i < 4; i++)
                rmax[i] = fmaxf(rmax[i], __shfl_xor_sync(0xffffffffu, rmax[i], off));

        #pragma unroll
        for (int i = 0; i < 4; i++) {
            float mnew = fmaxf(mrow[i], rmax[i]);
            float corr = __expf(mrow[i] - mnew);
            mrow[i] = mnew;
            float rs = 0.f;
            #pragma unroll
            for (int jj = 0; jj < 4; jj++) {
                float p = __expf(sc[i][jj] - mnew);
                sc[i][jj] = p;
                rs += p;
            }
            #pragma unroll
            for (int off = 8; off > 0; off >>= 1)
                rs += __shfl_xor_sync(0xffffffffu, rs, off);
            lsum[i] = lsum[i] * corr + rs;
            #pragma unroll
            for (int cI = 0; cI < 4; cI++) acc[i][cI] *= corr;
        }

        #pragma unroll
        for (int i = 0; i < 4; i++)
            #pragma unroll
            for (int jj = 0; jj < 4; jj++)
                Ps[tx * 4 + jj][ty * 4 + i] = sc[i][jj];
        __syncthreads();

        #pragma unroll 16
        for (int kk = 0; kk < 64; kk++) {
            float a[4], b[4];
            #pragma unroll
            for (int i = 0; i < 4; i++) a[i] = Ps[kk][ty * 4 + i];
            #pragma unroll
            for (int jj = 0; jj < 4; jj++) b[jj] = Vs[kk][tx * 4 + jj];
            #pragma unroll
            for (int i = 0; i < 4; i++)
                #pragma unroll
                for (int jj = 0; jj < 4; jj++)
                    acc[i][jj] += a[i] * b[jj];
        }
    }

    const int b_ = bh / HH, h = bh % HH;
    #pragma unroll
    for (int i = 0; i < 4; i++) {
        float inv = 1.f / lsum[i];
        int s = i0 + ty * 4 + i;
        float* orow = &g_Ctx[((size_t)(b_ * SS + s)) * DD + h * DKK];
        float4 o4 = make_float4(acc[i][0] * inv, acc[i][1] * inv,
                                acc[i][2] * inv, acc[i][3] * inv);
        *reinterpret_cast<float4*>(orow + tx * 4) = o4;
    }
}

// ---------------------------------------------------------------------------
extern "C" void kernel_launch(void* const* d_in, const int* in_sizes, int n_in,
                              void* d_out, int out_size)
{
    const float* q  = (const float*)d_in[0];
    const float* k  = (const float*)d_in[1];
    const float* v  = (const float*)d_in[2];
    const float* Wq = (const float*)d_in[3];
    const float* Wk = (const float*)d_in[4];
    const float* Wv = (const float*)d_in[5];
    const float* Wo = (const float*)d_in[6];
    const float* bo = (const float*)d_in[7];
    float* out = (float*)d_out;

    gemm_proj_bf16<<<dim3(MM / 128, DD / 128, 3), 256>>>(q, k, v, Wq, Wk, Wv);

    int smem_attn = (3 * 64 * 65 + 64 * 64) * (int)sizeof(float);   // ~66 KB
    cudaFuncSetAttribute(attn_kernel, cudaFuncAttributeMaxDynamicSharedMemorySize, smem_attn);
    attn_kernel<<<dim3(SS / 64, BHH), 256, smem_attn>>>();

    gemm_out_bf16<<<dim3(MM / 128, DD / 128), 256>>>(Wo, bo, out);
}

// round 10
// speedup vs baseline: 1.6455x; 1.4076x over previous
#include <cuda_runtime.h>
#include <cuda_bf16.h>
#include <cstdint>

// Problem constants
#define BB 2
#define SS 2048
#define DD 1024
#define HH 16
#define DKK 64
#define MM (BB*SS)      // 4096
#define BHH (BB*HH)     // 32
#define KP  512         // k-pairs per row (1024/2)

// Scratch (device globals)
__device__ float g_Q[BHH*SS*DKK];
__device__ float g_K[BHH*SS*DKK];
__device__ float g_V[BHH*SS*DKK];
// packed bf16-pair planes (pair = (k_even, k_odd) in one uint32)
__device__ uint32_t g_Xh[3*MM*KP],  g_Xl[3*MM*KP];    // inputs q,k,v: [which][m][kp]
__device__ uint32_t g_Wth[3*DD*KP], g_Wtl[3*DD*KP];   // W transposed: [which][n=h*64+dk][kp=d/2]
__device__ uint32_t g_Woh[DD*KP],   g_Wol[DD*KP];     // Wo: [n][kp=c/2]
__device__ uint32_t g_Ch[MM*KP],    g_Cl[MM*KP];      // attention out: [m][kp=c/2]

// ---------------------------------------------------------------------------
// helpers
// ---------------------------------------------------------------------------
__device__ __forceinline__ void mma_bf16(float c[4], const uint32_t a[4], const uint32_t b[2]) {
    asm volatile(
        "mma.sync.aligned.m16n8k16.row.col.f32.bf16.bf16.f32 "
        "{%0,%1,%2,%3}, {%4,%5,%6,%7}, {%8,%9}, {%0,%1,%2,%3};\n"
        : "+f"(c[0]), "+f"(c[1]), "+f"(c[2]), "+f"(c[3])
        : "r"(a[0]), "r"(a[1]), "r"(a[2]), "r"(a[3]), "r"(b[0]), "r"(b[1]));
}
__device__ __forceinline__ void split2(float x0, float x1, uint32_t& hi, uint32_t& lo) {
    __nv_bfloat16 h0 = __float2bfloat16(x0);
    __nv_bfloat16 h1 = __float2bfloat16(x1);
    __nv_bfloat16 l0 = __float2bfloat16(x0 - __bfloat162float(h0));
    __nv_bfloat16 l1 = __float2bfloat16(x1 - __bfloat162float(h1));
    hi = (uint32_t)__bfloat16_as_ushort(h0) | ((uint32_t)__bfloat16_as_ushort(h1) << 16);
    lo = (uint32_t)__bfloat16_as_ushort(l0) | ((uint32_t)__bfloat16_as_ushort(l1) << 16);
}
#define CP_ASYNC16(dst32, src) \
    asm volatile("cp.async.cg.shared.global [%0], [%1], 16;\n" :: "r"(dst32), "l"(src) : "memory")
#define CP_COMMIT() asm volatile("cp.async.commit_group;\n" ::: "memory")
#define CP_WAIT0()  asm volatile("cp.async.wait_group 0;\n" ::: "memory")

// ---------------------------------------------------------------------------
// convert kernels (one-shot fp32 -> packed bf16 hi/lo)
// ---------------------------------------------------------------------------
__global__ void convert_x(const float* __restrict__ q, const float* __restrict__ k,
                          const float* __restrict__ v) {
    int idx = blockIdx.x * 256 + threadIdx.x;           // 3*4096*256
    int which = idx / (MM * 256);
    int rem = idx - which * (MM * 256);
    int m = rem >> 8, i = rem & 255;
    const float* X = (which == 0) ? q : (which == 1) ? k : v;
    float4 f = *reinterpret_cast<const float4*>(X + (size_t)m * DD + i * 4);
    uint32_t h0, l0, h1, l1;
    split2(f.x, f.y, h0, l0);
    split2(f.z, f.w, h1, l1);
    size_t o = (size_t)which * MM * KP + (size_t)m * KP + i * 2;
    *reinterpret_cast<uint2*>(&g_Xh[o]) = make_uint2(h0, h1);
    *reinterpret_cast<uint2*>(&g_Xl[o]) = make_uint2(l0, l1);
}

__global__ void convert_w(const float* __restrict__ Wq, const float* __restrict__ Wk,
                          const float* __restrict__ Wv) {
    int idx = blockIdx.x * 256 + threadIdx.x;           // 3*16*512*16
    int which = idx / (HH * KP * 16);
    int rem = idx - which * (HH * KP * 16);
    int dk4 = rem & 15;
    int kp = (rem >> 4) & 511;
    int h = rem >> 13;
    const float* W = (which == 0) ? Wq : (which == 1) ? Wk : Wv;
    const float* r0 = W + ((size_t)h * DD + 2 * kp) * DKK + dk4 * 4;
    float4 a = *reinterpret_cast<const float4*>(r0);
    float4 b = *reinterpret_cast<const float4*>(r0 + DKK);
    float ax[4] = {a.x, a.y, a.z, a.w};
    float bx[4] = {b.x, b.y, b.z, b.w};
    #pragma unroll
    for (int e = 0; e < 4; e++) {
        uint32_t hi, lo;
        split2(ax[e], bx[e], hi, lo);
        int n = h * 64 + dk4 * 4 + e;
        size_t o = (size_t)which * DD * KP + (size_t)n * KP + kp;
        g_Wth[o] = hi;
        g_Wtl[o] = lo;
    }
}

__global__ void convert_wo(const float* __restrict__ Wo) {
    int idx = blockIdx.x * 256 + threadIdx.x;           // 1024*256
    int n = idx >> 8, i = idx & 255;
    float4 f = *reinterpret_cast<const float4*>(Wo + (size_t)n * DD + i * 4);
    uint32_t h0, l0, h1, l1;
    split2(f.x, f.y, h0, l0);
    split2(f.z, f.w, h1, l1);
    size_t o = (size_t)n * KP + i * 2;
    *reinterpret_cast<uint2*>(&g_Woh[o]) = make_uint2(h0, h1);
    *reinterpret_cast<uint2*>(&g_Wol[o]) = make_uint2(l0, l1);
}

// ---------------------------------------------------------------------------
// GEMM core (bf16x3, cp.async double-buffered). BK=32 (16 kpairs), 32 stages.
// smem: 2 buffers x 4 planes x [128 rows][20 words] (16 used + 4 pad)
// plane order: A_h, A_l, B_h, B_l
// ---------------------------------------------------------------------------
#define PLANE_W 2560              // words per plane
#define BUF_W   (4*PLANE_W)       // words per buffer
#define SMEM_GEMM_BYTES (2*BUF_W*4)   // 81920

struct GemmPtrs { const uint32_t *Ah, *Al, *Bh, *Bl; };

__device__ __forceinline__ void gemm_issue(uint32_t smem_base, const GemmPtrs& P,
                                           int m0, int n0, int s, int b, int tid) {
    const int kp0 = s * 16;
    #pragma unroll
    for (int r = 0; r < 8; r++) {
        int c = tid + r * 256;
        int plane = c >> 9;
        int cc = c & 511;
        int row = cc >> 2, seg = cc & 3;
        const uint32_t* srcb;
        int grow;
        if (plane == 0)      { srcb = P.Ah; grow = m0 + row; }
        else if (plane == 1) { srcb = P.Al; grow = m0 + row; }
        else if (plane == 2) { srcb = P.Bh; grow = n0 + row; }
        else                 { srcb = P.Bl; grow = n0 + row; }
        const uint32_t* src = srcb + (size_t)grow * KP + kp0 + seg * 4;
        uint32_t dst = smem_base + ((b * BUF_W + plane * PLANE_W + row * 20 + seg * 4) << 2);
        CP_ASYNC16(dst, src);
    }
    CP_COMMIT();
}

__device__ __forceinline__ void gemm_compute(const uint32_t* smw, int b,
                                             int wm, int wn, int g, int tg,
                                             float acc[4][4][4]) {
    const uint32_t* Ah_s = smw + b * BUF_W;
    const uint32_t* Al_s = Ah_s + PLANE_W;
    const uint32_t* Bh_s = Ah_s + 2 * PLANE_W;
    const uint32_t* Bl_s = Ah_s + 3 * PLANE_W;
    #pragma unroll
    for (int kf = 0; kf < 2; kf++) {
        const int kb = kf * 8;
        uint32_t bh[4][2], bl[4][2];
        #pragma unroll
        for (int nf = 0; nf < 4; nf++) {
            int nb = wn * 32 + nf * 8 + g;
            bh[nf][0] = Bh_s[nb*20 + kb+tg]; bh[nf][1] = Bh_s[nb*20 + kb+tg+4];
            bl[nf][0] = Bl_s[nb*20 + kb+tg]; bl[nf][1] = Bl_s[nb*20 + kb+tg+4];
        }
        #pragma unroll
        for (int mf = 0; mf < 4; mf++) {
            int mb = wm * 64 + mf * 16 + g;
            uint32_t ah[4], al[4];
            ah[0] = Ah_s[(mb  )*20 + kb+tg  ]; al[0] = Al_s[(mb  )*20 + kb+tg  ];
            ah[1] = Ah_s[(mb+8)*20 + kb+tg  ]; al[1] = Al_s[(mb+8)*20 + kb+tg  ];
            ah[2] = Ah_s[(mb  )*20 + kb+tg+4]; al[2] = Al_s[(mb  )*20 + kb+tg+4];
            ah[3] = Ah_s[(mb+8)*20 + kb+tg+4]; al[3] = Al_s[(mb+8)*20 + kb+tg+4];
            #pragma unroll
            for (int nf = 0; nf < 4; nf++) {
                mma_bf16(acc[mf][nf], ah, bh[nf]);
                mma_bf16(acc[mf][nf], ah, bl[nf]);
                mma_bf16(acc[mf][nf], al, bh[nf]);
            }
        }
    }
}

// ---------------------------------------------------------------------------
// Kernel: QKV projections. grid (32, 8, 3), block 256.
// ---------------------------------------------------------------------------
__global__ __launch_bounds__(256, 2) void gemm_proj_tc(void)
{
    extern __shared__ uint32_t smw[];
    const int which = blockIdx.z;
    GemmPtrs P;
    P.Ah = g_Xh + (size_t)which * MM * KP;
    P.Al = g_Xl + (size_t)which * MM * KP;
    P.Bh = g_Wth + (size_t)which * DD * KP;
    P.Bl = g_Wtl + (size_t)which * DD * KP;
    float* Out = (which == 0) ? g_Q : (which == 1) ? g_K : g_V;

    const int m0 = blockIdx.x * 128;
    const int n0 = blockIdx.y * 128;
    const int tid = threadIdx.x;
    const int wid = tid >> 5, lane = tid & 31;
    const int wm = wid >> 2, wn = wid & 3;
    const int g = lane >> 2, tg = lane & 3;
    const uint32_t smem_base = (uint32_t)__cvta_generic_to_shared(smw);

    float acc[4][4][4] = {};

    gemm_issue(smem_base, P, m0, n0, 0, 0, tid);
    for (int s = 0; s < 32; s++) {
        const int b = s & 1;
        CP_WAIT0();
        __syncthreads();
        if (s + 1 < 32) gemm_issue(smem_base, P, m0, n0, s + 1, b ^ 1, tid);
        gemm_compute(smw, b, wm, wn, g, tg, acc);
        __syncthreads();
    }

    // epilogue: scatter to Out[bh][s][dk] (validated mapping)
    #pragma unroll
    for (int mf = 0; mf < 4; mf++) {
        int r0 = m0 + wm * 64 + mf * 16 + g;
        #pragma unroll
        for (int nf = 0; nf < 4; nf++) {
            int c = n0 + wn * 32 + nf * 8 + 2 * tg;
            int h = c >> 6, dk = c & 63;
            {
                int b_ = r0 >> 11, sI = r0 & 2047;
                float2 o = make_float2(acc[mf][nf][0], acc[mf][nf][1]);
                *reinterpret_cast<float2*>(&Out[(((size_t)(b_ * HH + h)) * SS + sI) * DKK + dk]) = o;
            }
            {
                int r1 = r0 + 8;
                int b_ = r1 >> 11, sI = r1 & 2047;
                float2 o = make_float2(acc[mf][nf][2], acc[mf][nf][3]);
                *reinterpret_cast<float2*>(&Out[(((size_t)(b_ * HH + h)) * SS + sI) * DKK + dk]) = o;
            }
        }
    }
}

// ---------------------------------------------------------------------------
// Kernel: output projection. grid (32, 8), block 256.
// ---------------------------------------------------------------------------
__global__ __launch_bounds__(256, 2) void gemm_out_tc(const float* __restrict__ bo,
                                                      float* __restrict__ out)
{
    extern __shared__ uint32_t smw[];
    GemmPtrs P;
    P.Ah = g_Ch; P.Al = g_Cl; P.Bh = g_Woh; P.Bl = g_Wol;

    const int m0 = blockIdx.x * 128;
    const int n0 = blockIdx.y * 128;
    const int tid = threadIdx.x;
    const int wid = tid >> 5, lane = tid & 31;
    const int wm = wid >> 2, wn = wid & 3;
    const int g = lane >> 2, tg = lane & 3;
    const uint32_t smem_base = (uint32_t)__cvta_generic_to_shared(smw);

    float acc[4][4][4] = {};

    gemm_issue(smem_base, P, m0, n0, 0, 0, tid);
    for (int s = 0; s < 32; s++) {
        const int b = s & 1;
        CP_WAIT0();
        __syncthreads();
        if (s + 1 < 32) gemm_issue(smem_base, P, m0, n0, s + 1, b ^ 1, tid);
        gemm_compute(smw, b, wm, wn, g, tg, acc);
        __syncthreads();
    }

    #pragma unroll
    for (int mf = 0; mf < 4; mf++) {
        int r0 = m0 + wm * 64 + mf * 16 + g;
        #pragma unroll
        for (int nf = 0; nf < 4; nf++) {
            int c = n0 + wn * 32 + nf * 8 + 2 * tg;
            float2 bb = *reinterpret_cast<const float2*>(&bo[c]);
            float2 o0 = make_float2(acc[mf][nf][0] + bb.x, acc[mf][nf][1] + bb.y);
            float2 o1 = make_float2(acc[mf][nf][2] + bb.x, acc[mf][nf][3] + bb.y);
            *reinterpret_cast<float2*>(&out[(size_t)r0 * DD + c]) = o0;
            *reinterpret_cast<float2*>(&out[(size_t)(r0 + 8) * DD + c]) = o1;
        }
    }
}

// ---------------------------------------------------------------------------
// Kernel 2: causal flash attention (known-good R2 compute; epilogue now emits
// packed bf16 hi/lo Ctx planes). grid: (S/64, B*H), block 256.
// ---------------------------------------------------------------------------
__global__ __launch_bounds__(256) void attn_kernel()
{
    extern __shared__ float sm[];
    float (*Qs)[65] = (float(*)[65])(sm);
    float (*Ks)[65] = (float(*)[65])(sm + 64 * 65);
    float (*Ps)[65] = (float(*)[65])(sm + 2 * 64 * 65);
    float (*Vs)[64] = (float(*)[64])(sm + 3 * 64 * 65);

    const int bh = blockIdx.y;
    const int qi = (gridDim.x - 1) - blockIdx.x;
    const int i0 = qi * 64;
    const float* Qg = g_Q + (size_t)bh * SS * DKK;
    const float* Kg = g_K + (size_t)bh * SS * DKK;
    const float* Vg = g_V + (size_t)bh * SS * DKK;

    const int tid = threadIdx.x;
    const int tx = tid & 15, ty = tid >> 4;

    #pragma unroll
    for (int rep = 0; rep < 4; rep++) {
        int idx = tid + rep * 256;
        int r = idx >> 4, c4 = idx & 15;
        float4 a4 = *reinterpret_cast<const float4*>(&Qg[(i0 + r) * DKK + c4 * 4]);
        Qs[c4*4+0][r] = a4.x; Qs[c4*4+1][r] = a4.y;
        Qs[c4*4+2][r] = a4.z; Qs[c4*4+3][r] = a4.w;
    }

    float acc[4][4] = {};
    float mrow[4], lsum[4];
    #pragma unroll
    for (int i = 0; i < 4; i++) { mrow[i] = -1e30f; lsum[i] = 0.f; }
    const float scale = 0.125f;

    const int ntiles = qi + 1;
    for (int j = 0; j < ntiles; j++) {
        const int j0 = j * 64;
        __syncthreads();
        #pragma unroll
        for (int rep = 0; rep < 4; rep++) {
            int idx = tid + rep * 256;
            int r = idx >> 4, c4 = idx & 15;
            float4 a4 = *reinterpret_cast<const float4*>(&Kg[(j0 + r) * DKK + c4 * 4]);
            Ks[c4*4+0][r] = a4.x; Ks[c4*4+1][r] = a4.y;
            Ks[c4*4+2][r] = a4.z; Ks[c4*4+3][r] = a4.w;
        }
        #pragma unroll
        for (int rep = 0; rep < 4; rep++) {
            int idx = tid + rep * 256;
            int t = idx >> 4, c4 = idx & 15;
            *reinterpret_cast<float4*>(&Vs[t][c4 * 4]) =
                *reinterpret_cast<const float4*>(&Vg[(j0 + t) * DKK + c4 * 4]);
        }
        __syncthreads();

        float sc[4][4] = {};
        #pragma unroll 16
        for (int kk = 0; kk < 64; kk++) {
            float a[4], b[4];
            #pragma unroll
            for (int i = 0; i < 4; i++) a[i] = Qs[kk][ty * 4 + i];
            #pragma unroll
            for (int jj = 0; jj < 4; jj++) b[jj] = Ks[kk][tx * 4 + jj];
            #pragma unroll
            for (int i = 0; i < 4; i++)
                #pragma unroll
                for (int jj = 0; jj < 4; jj++)
                    sc[i][jj] += a[i] * b[jj];
        }

        const bool diag = (j == qi);
        float rmax[4];
        #pragma unroll
        for (int i = 0; i < 4; i++) {
            rmax[i] = -1e30f;
            #pragma unroll
            for (int jj = 0; jj < 4; jj++) {
                float s_ = sc[i][jj] * scale;
                if (diag && (j0 + tx * 4 + jj) > (i0 + ty * 4 + i)) s_ = -1e30f;
                sc[i][jj] = s_;
                rmax[i] = fmaxf(rmax[i], s_);
            }
        }
        #pragma unroll
        for (int off = 8; off > 0; off >>= 1)
            #pragma unroll
            for (int i = 0; i < 4; i++)
                rmax[i] = fmaxf(rmax[i], __shfl_xor_sync(0xffffffffu, rmax[i], off));

        #pragma unroll
        for (int i = 0; i < 4; i++) {
            float mnew = fmaxf(mrow[i], rmax[i]);
            float corr = __expf(mrow[i] - mnew);
            mrow[i] = mnew;
            float rs = 0.f;
            #pragma unroll
            for (int jj = 0; jj < 4; jj++) {
                float p = __expf(sc[i][jj] - mnew);
                sc[i][jj] = p;
                rs += p;
            }
            #pragma unroll
            for (int off = 8; off > 0; off >>= 1)
                rs += __shfl_xor_sync(0xffffffffu, rs, off);
            lsum[i] = lsum[i] * corr + rs;
            #pragma unroll
            for (int cI = 0; cI < 4; cI++) acc[i][cI] *= corr;
        }

        #pragma unroll
        for (int i = 0; i < 4; i++)
            #pragma unroll
            for (int jj = 0; jj < 4; jj++)
                Ps[tx * 4 + jj][ty * 4 + i] = sc[i][jj];
        __syncthreads();

        #pragma unroll 16
        for (int kk = 0; kk < 64; kk++) {
            float a[4], b[4];
            #pragma unroll
            for (int i = 0; i < 4; i++) a[i] = Ps[kk][ty * 4 + i];
            #pragma unroll
            for (int jj = 0; jj < 4; jj++) b[jj] = Vs[kk][tx * 4 + jj];
            #pragma unroll
            for (int i = 0; i < 4; i++)
                #pragma unroll
                for (int jj = 0; jj < 4; jj++)
                    acc[i][jj] += a[i] * b[jj];
        }
    }

    // epilogue: divide by l; write packed bf16 hi/lo Ctx planes at [m][h*32 + tx*2]
    const int b_ = bh / HH, h = bh % HH;
    #pragma unroll
    for (int i = 0; i < 4; i++) {
        float inv = 1.f / lsum[i];
        int s = i0 + ty * 4 + i;
        float o0 = acc[i][0] * inv, o1 = acc[i][1] * inv;
        float o2 = acc[i][2] * inv, o3 = acc[i][3] * inv;
        uint32_t h0, l0, h1, l1;
        split2(o0, o1, h0, l0);
        split2(o2, o3, h1, l1);
        size_t o = ((size_t)(b_ * SS + s)) * KP + h * 32 + tx * 2;
        *reinterpret_cast<uint2*>(&g_Ch[o]) = make_uint2(h0, h1);
        *reinterpret_cast<uint2*>(&g_Cl[o]) = make_uint2(l0, l1);
    }
}

// ---------------------------------------------------------------------------
extern "C" void kernel_launch(void* const* d_in, const int* in_sizes, int n_in,
                              void* d_out, int out_size)
{
    const float* q  = (const float*)d_in[0];
    const float* k  = (const float*)d_in[1];
    const float* v  = (const float*)d_in[2];
    const float* Wq = (const float*)d_in[3];
    const float* Wk = (const float*)d_in[4];
    const float* Wv = (const float*)d_in[5];
    const float* Wo = (const float*)d_in[6];
    const float* bo = (const float*)d_in[7];
    float* out = (float*)d_out;

    cudaFuncSetAttribute(gemm_proj_tc, cudaFuncAttributeMaxDynamicSharedMemorySize, SMEM_GEMM_BYTES);
    cudaFuncSetAttribute(gemm_out_tc,  cudaFuncAttributeMaxDynamicSharedMemorySize, SMEM_GEMM_BYTES);

    convert_x<<<3 * MM * 256 / 256, 256>>>(q, k, v);
    convert_w<<<3 * HH * KP * 16 / 256, 256>>>(Wq, Wk, Wv);
    convert_wo<<<DD * 256 / 256, 256>>>(Wo);

    gemm_proj_tc<<<dim3(MM / 128, DD / 128, 3), 256, SMEM_GEMM_BYTES>>>();

    int smem_attn = (3 * 64 * 65 + 64 * 64) * (int)sizeof(float);   // ~66 KB
    cudaFuncSetAttribute(attn_kernel, cudaFuncAttributeMaxDynamicSharedMemorySize, smem_attn);
    attn_kernel<<<dim3(SS / 64, BHH), 256, smem_attn>>>();

    gemm_out_tc<<<dim3(MM / 128, DD / 128), 256, SMEM_GEMM_BYTES>>>(bo, out);
}

// round 12
// speedup vs baseline: 2.7948x; 1.6985x over previous
#include <cuda_runtime.h>
#include <cuda_bf16.h>
#include <cstdint>

// Problem constants
#define BB 2
#define SS 2048
#define DD 1024
#define HH 16
#define DKK 64
#define MM (BB*SS)      // 4096
#define BHH (BB*HH)     // 32
#define KP  512         // k-pairs per 1024-wide row
#define DKP 32          // dk-pairs per head (64/2)

// Scratch (device globals)
__device__ float g_V[BHH*SS*DKK];                     // [bh][t][dk] fp32 (pre-transpose)
// packed bf16-pair planes
__device__ uint32_t g_Xh[3*MM*KP],  g_Xl[3*MM*KP];    // inputs q,k,v: [which][m][kp]
__device__ uint32_t g_Wth[3*DD*KP], g_Wtl[3*DD*KP];   // W transposed: [which][n][kp]
__device__ uint32_t g_Woh[DD*KP],   g_Wol[DD*KP];     // Wo: [n][kp]
__device__ uint32_t g_Ch[MM*KP],    g_Cl[MM*KP];      // attention out: [m][kp]
__device__ uint32_t g_Qph[BHH*SS*DKP], g_Qpl[BHH*SS*DKP]; // Q pairs (pre-scaled 1/8)
__device__ uint32_t g_Kph[BHH*SS*DKP], g_Kpl[BHH*SS*DKP]; // K pairs
__device__ uint32_t g_Vth[BHH*DKK*(SS/2)], g_Vtl[BHH*DKK*(SS/2)]; // V^T: [bh][dk][tp]

// ---------------------------------------------------------------------------
// helpers
// ---------------------------------------------------------------------------
__device__ __forceinline__ void mma_bf16(float c[4], const uint32_t a[4], const uint32_t b[2]) {
    asm volatile(
        "mma.sync.aligned.m16n8k16.row.col.f32.bf16.bf16.f32 "
        "{%0,%1,%2,%3}, {%4,%5,%6,%7}, {%8,%9}, {%0,%1,%2,%3};\n"
        : "+f"(c[0]), "+f"(c[1]), "+f"(c[2]), "+f"(c[3])
        : "r"(a[0]), "r"(a[1]), "r"(a[2]), "r"(a[3]), "r"(b[0]), "r"(b[1]));
}
__device__ __forceinline__ void split2(float x0, float x1, uint32_t& hi, uint32_t& lo) {
    __nv_bfloat16 h0 = __float2bfloat16(x0);
    __nv_bfloat16 h1 = __float2bfloat16(x1);
    __nv_bfloat16 l0 = __float2bfloat16(x0 - __bfloat162float(h0));
    __nv_bfloat16 l1 = __float2bfloat16(x1 - __bfloat162float(h1));
    hi = (uint32_t)__bfloat16_as_ushort(h0) | ((uint32_t)__bfloat16_as_ushort(h1) << 16);
    lo = (uint32_t)__bfloat16_as_ushort(l0) | ((uint32_t)__bfloat16_as_ushort(l1) << 16);
}
#define CP_ASYNC16(dst32, src) \
    asm volatile("cp.async.cg.shared.global [%0], [%1], 16;\n" :: "r"(dst32), "l"(src) : "memory")
#define CP_COMMIT() asm volatile("cp.async.commit_group;\n" ::: "memory")
#define CP_WAIT0()  asm volatile("cp.async.wait_group 0;\n" ::: "memory")

// ---------------------------------------------------------------------------
// convert kernels (one-shot fp32 -> packed bf16 hi/lo)
// ---------------------------------------------------------------------------
__global__ void convert_x(const float* __restrict__ q, const float* __restrict__ k,
                          const float* __restrict__ v) {
    int idx = blockIdx.x * 256 + threadIdx.x;
    int which = idx / (MM * 256);
    int rem = idx - which * (MM * 256);
    int m = rem >> 8, i = rem & 255;
    const float* X = (which == 0) ? q : (which == 1) ? k : v;
    float4 f = *reinterpret_cast<const float4*>(X + (size_t)m * DD + i * 4);
    uint32_t h0, l0, h1, l1;
    split2(f.x, f.y, h0, l0);
    split2(f.z, f.w, h1, l1);
    size_t o = (size_t)which * MM * KP + (size_t)m * KP + i * 2;
    *reinterpret_cast<uint2*>(&g_Xh[o]) = make_uint2(h0, h1);
    *reinterpret_cast<uint2*>(&g_Xl[o]) = make_uint2(l0, l1);
}

__global__ void convert_w(const float* __restrict__ Wq, const float* __restrict__ Wk,
                          const float* __restrict__ Wv) {
    int idx = blockIdx.x * 256 + threadIdx.x;
    int which = idx / (HH * KP * 16);
    int rem = idx - which * (HH * KP * 16);
    int dk4 = rem & 15;
    int kp = (rem >> 4) & 511;
    int h = rem >> 13;
    const float* W = (which == 0) ? Wq : (which == 1) ? Wk : Wv;
    const float* r0 = W + ((size_t)h * DD + 2 * kp) * DKK + dk4 * 4;
    float4 a = *reinterpret_cast<const float4*>(r0);
    float4 b = *reinterpret_cast<const float4*>(r0 + DKK);
    float ax[4] = {a.x, a.y, a.z, a.w};
    float bx[4] = {b.x, b.y, b.z, b.w};
    #pragma unroll
    for (int e = 0; e < 4; e++) {
        uint32_t hi, lo;
        split2(ax[e], bx[e], hi, lo);
        int n = h * 64 + dk4 * 4 + e;
        size_t o = (size_t)which * DD * KP + (size_t)n * KP + kp;
        g_Wth[o] = hi;
        g_Wtl[o] = lo;
    }
}

__global__ void convert_wo(const float* __restrict__ Wo) {
    int idx = blockIdx.x * 256 + threadIdx.x;
    int n = idx >> 8, i = idx & 255;
    float4 f = *reinterpret_cast<const float4*>(Wo + (size_t)n * DD + i * 4);
    uint32_t h0, l0, h1, l1;
    split2(f.x, f.y, h0, l0);
    split2(f.z, f.w, h1, l1);
    size_t o = (size_t)n * KP + i * 2;
    *reinterpret_cast<uint2*>(&g_Woh[o]) = make_uint2(h0, h1);
    *reinterpret_cast<uint2*>(&g_Wol[o]) = make_uint2(l0, l1);
}

// transpose+split V: [bh][t][dk] fp32 -> [bh][dk][tp] bf16 pairs (pair along t)
// grid (SS/32, BHH), block 256
__global__ void convert_vt() {
    __shared__ float sm[32][65];
    const int bh = blockIdx.y;
    const int t0 = blockIdx.x * 32;
    const int tid = threadIdx.x;
    const float* Vg = g_V + (size_t)bh * SS * DKK;
    #pragma unroll
    for (int r = 0; r < 8; r++) {
        int idx = tid + r * 256;
        int t = idx >> 6, dk = idx & 63;
        sm[t][dk] = Vg[(size_t)(t0 + t) * DKK + dk];
    }
    __syncthreads();
    const int dk = tid >> 2;
    const int pg = tid & 3;
    uint32_t* Vth = g_Vth + (size_t)bh * DKK * (SS/2) + (size_t)dk * (SS/2) + t0/2;
    uint32_t* Vtl = g_Vtl + (size_t)bh * DKK * (SS/2) + (size_t)dk * (SS/2) + t0/2;
    #pragma unroll
    for (int e = 0; e < 4; e++) {
        int p = pg * 4 + e;
        uint32_t hi, lo;
        split2(sm[2*p][dk], sm[2*p+1][dk], hi, lo);
        Vth[p] = hi;
        Vtl[p] = lo;
    }
}

// ---------------------------------------------------------------------------
// GEMM core (bf16x3, cp.async double-buffered) -- validated R10 machinery
// ---------------------------------------------------------------------------
#define PLANE_W 2560
#define BUF_W   (4*PLANE_W)
#define SMEM_GEMM_BYTES (2*BUF_W*4)

struct GemmPtrs { const uint32_t *Ah, *Al, *Bh, *Bl; };

__device__ __forceinline__ void gemm_issue(uint32_t smem_base, const GemmPtrs& P,
                                           int m0, int n0, int s, int b, int tid) {
    const int kp0 = s * 16;
    #pragma unroll
    for (int r = 0; r < 8; r++) {
        int c = tid + r * 256;
        int plane = c >> 9;
        int cc = c & 511;
        int row = cc >> 2, seg = cc & 3;
        const uint32_t* srcb;
        int grow;
        if (plane == 0)      { srcb = P.Ah; grow = m0 + row; }
        else if (plane == 1) { srcb = P.Al; grow = m0 + row; }
        else if (plane == 2) { srcb = P.Bh; grow = n0 + row; }
        else                 { srcb = P.Bl; grow = n0 + row; }
        const uint32_t* src = srcb + (size_t)grow * KP + kp0 + seg * 4;
        uint32_t dst = smem_base + ((b * BUF_W + plane * PLANE_W + row * 20 + seg * 4) << 2);
        CP_ASYNC16(dst, src);
    }
    CP_COMMIT();
}

__device__ __forceinline__ void gemm_compute(const uint32_t* smw, int b,
                                             int wm, int wn, int g, int tg,
                                             float acc[4][4][4]) {
    const uint32_t* Ah_s = smw + b * BUF_W;
    const uint32_t* Al_s = Ah_s + PLANE_W;
    const uint32_t* Bh_s = Ah_s + 2 * PLANE_W;
    const uint32_t* Bl_s = Ah_s + 3 * PLANE_W;
    #pragma unroll
    for (int kf = 0; kf < 2; kf++) {
        const int kb = kf * 8;
        uint32_t bh[4][2], bl[4][2];
        #pragma unroll
        for (int nf = 0; nf < 4; nf++) {
            int nb = wn * 32 + nf * 8 + g;
            bh[nf][0] = Bh_s[nb*20 + kb+tg]; bh[nf][1] = Bh_s[nb*20 + kb+tg+4];
            bl[nf][0] = Bl_s[nb*20 + kb+tg]; bl[nf][1] = Bl_s[nb*20 + kb+tg+4];
        }
        #pragma unroll
        for (int mf = 0; mf < 4; mf++) {
            int mb = wm * 64 + mf * 16 + g;
            uint32_t ah[4], al[4];
            ah[0] = Ah_s[(mb  )*20 + kb+tg  ]; al[0] = Al_s[(mb  )*20 + kb+tg  ];
            ah[1] = Ah_s[(mb+8)*20 + kb+tg  ]; al[1] = Al_s[(mb+8)*20 + kb+tg  ];
            ah[2] = Ah_s[(mb  )*20 + kb+tg+4]; al[2] = Al_s[(mb  )*20 + kb+tg+4];
            ah[3] = Ah_s[(mb+8)*20 + kb+tg+4]; al[3] = Al_s[(mb+8)*20 + kb+tg+4];
            #pragma unroll
            for (int nf = 0; nf < 4; nf++) {
                mma_bf16(acc[mf][nf], ah, bh[nf]);
                mma_bf16(acc[mf][nf], ah, bl[nf]);
                mma_bf16(acc[mf][nf], al, bh[nf]);
            }
        }
    }
}

// ---------------------------------------------------------------------------
// Kernel: QKV projections. grid (32, 8, 3), block 256.
// Q/K outputs -> pre-split bf16 pairs (Q pre-scaled by 1/8); V -> fp32.
// ---------------------------------------------------------------------------
__global__ __launch_bounds__(256, 2) void gemm_proj_tc(void)
{
    extern __shared__ uint32_t smw[];
    const int which = blockIdx.z;
    GemmPtrs P;
    P.Ah = g_Xh + (size_t)which * MM * KP;
    P.Al = g_Xl + (size_t)which * MM * KP;
    P.Bh = g_Wth + (size_t)which * DD * KP;
    P.Bl = g_Wtl + (size_t)which * DD * KP;

    const int m0 = blockIdx.x * 128;
    const int n0 = blockIdx.y * 128;
    const int tid = threadIdx.x;
    const int wid = tid >> 5, lane = tid & 31;
    const int wm = wid >> 2, wn = wid & 3;
    const int g = lane >> 2, tg = lane & 3;
    const uint32_t smem_base = (uint32_t)__cvta_generic_to_shared(smw);

    float acc[4][4][4] = {};

    gemm_issue(smem_base, P, m0, n0, 0, 0, tid);
    for (int s = 0; s < 32; s++) {
        const int b = s & 1;
        CP_WAIT0();
        __syncthreads();
        if (s + 1 < 32) gemm_issue(smem_base, P, m0, n0, s + 1, b ^ 1, tid);
        gemm_compute(smw, b, wm, wn, g, tg, acc);
        __syncthreads();
    }

    const float scale = (which == 0) ? 0.125f : 1.0f;
    #pragma unroll
    for (int mf = 0; mf < 4; mf++) {
        int r0 = m0 + wm * 64 + mf * 16 + g;
        #pragma unroll
        for (int nf = 0; nf < 4; nf++) {
            int c = n0 + wn * 32 + nf * 8 + 2 * tg;
            int h = c >> 6, dk = c & 63;
            if (which == 2) {
                int b_ = r0 >> 11, sI = r0 & 2047;
                float2 o = make_float2(acc[mf][nf][0], acc[mf][nf][1]);
                *reinterpret_cast<float2*>(&g_V[(((size_t)(b_ * HH + h)) * SS + sI) * DKK + dk]) = o;
                int r1 = r0 + 8;
                b_ = r1 >> 11; sI = r1 & 2047;
                o = make_float2(acc[mf][nf][2], acc[mf][nf][3]);
                *reinterpret_cast<float2*>(&g_V[(((size_t)(b_ * HH + h)) * SS + sI) * DKK + dk]) = o;
            } else {
                uint32_t* Oh = (which == 0) ? g_Qph : g_Kph;
                uint32_t* Ol = (which == 0) ? g_Qpl : g_Kpl;
                {
                    int b_ = r0 >> 11, sI = r0 & 2047;
                    size_t o = (((size_t)(b_ * HH + h)) * SS + sI) * DKP + (dk >> 1);
                    uint32_t hi, lo;
                    split2(acc[mf][nf][0] * scale, acc[mf][nf][1] * scale, hi, lo);
                    Oh[o] = hi; Ol[o] = lo;
                }
                {
                    int r1 = r0 + 8;
                    int b_ = r1 >> 11, sI = r1 & 2047;
                    size_t o = (((size_t)(b_ * HH + h)) * SS + sI) * DKP + (dk >> 1);
                    uint32_t hi, lo;
                    split2(acc[mf][nf][2] * scale, acc[mf][nf][3] * scale, hi, lo);
                    Oh[o] = hi; Ol[o] = lo;
                }
            }
        }
    }
}

// ---------------------------------------------------------------------------
// Kernel: output projection. grid (32, 8), block 256. (validated R10)
// ---------------------------------------------------------------------------
__global__ __launch_bounds__(256, 2) void gemm_out_tc(const float* __restrict__ bo,
                                                      float* __restrict__ out)
{
    extern __shared__ uint32_t smw[];
    GemmPtrs P;
    P.Ah = g_Ch; P.Al = g_Cl; P.Bh = g_Woh; P.Bl = g_Wol;

    const int m0 = blockIdx.x * 128;
    const int n0 = blockIdx.y * 128;
    const int tid = threadIdx.x;
    const int wid = tid >> 5, lane = tid & 31;
    const int wm = wid >> 2, wn = wid & 3;
    const int g = lane >> 2, tg = lane & 3;
    const uint32_t smem_base = (uint32_t)__cvta_generic_to_shared(smw);

    float acc[4][4][4] = {};

    gemm_issue(smem_base, P, m0, n0, 0, 0, tid);
    for (int s = 0; s < 32; s++) {
        const int b = s & 1;
        CP_WAIT0();
        __syncthreads();
        if (s + 1 < 32) gemm_issue(smem_base, P, m0, n0, s + 1, b ^ 1, tid);
        gemm_compute(smw, b, wm, wn, g, tg, acc);
        __syncthreads();
    }

    #pragma unroll
    for (int mf = 0; mf < 4; mf++) {
        int r0 = m0 + wm * 64 + mf * 16 + g;
        #pragma unroll
        for (int nf = 0; nf < 4; nf++) {
            int c = n0 + wn * 32 + nf * 8 + 2 * tg;
            float2 bb = *reinterpret_cast<const float2*>(&bo[c]);
            float2 o0 = make_float2(acc[mf][nf][0] + bb.x, acc[mf][nf][1] + bb.y);
            float2 o1 = make_float2(acc[mf][nf][2] + bb.x, acc[mf][nf][3] + bb.y);
            *reinterpret_cast<float2*>(&out[(size_t)r0 * DD + c]) = o0;
            *reinterpret_cast<float2*>(&out[(size_t)(r0 + 8) * DD + c]) = o1;
        }
    }
}

// ---------------------------------------------------------------------------
// Kernel: tensor-core causal flash attention (FIXED warp layout).
// grid (32, 32): (q-tile heavy-first, bh). block 128 = 4 warps, 1x4 m-split:
// warp wid owns rows wid*16..wid*16+15 and ALL 64 columns -> full row stats
// live in one warp (shfl over tg + nf register loop).
// smem planes (64 rows x 36 words): 0 Qh,1 Ql,2 Kh,3 Kl,4 Vh,5 Vl,6 Ph,7 Pl
// ---------------------------------------------------------------------------
#define PLW 36
#define APL (64*PLW)
#define SMEM_ATTN_BYTES (8*APL*4)   // 73728

__global__ __launch_bounds__(128) void attn_tc()
{
    extern __shared__ uint32_t smw[];
    const int bh = blockIdx.y;
    const int qi = 31 - blockIdx.x;        // heavy tiles first
    const int i0 = qi * 64;
    const int tid = threadIdx.x;
    const int wid = tid >> 5, lane = tid & 31;
    const int g = lane >> 2, tg = lane & 3;
    const int mb = wid * 16;               // warp's row base within tile
    const uint32_t sb = (uint32_t)__cvta_generic_to_shared(smw);

    const uint32_t* Qh_g = g_Qph + (size_t)bh * SS * DKP;
    const uint32_t* Ql_g = g_Qpl + (size_t)bh * SS * DKP;
    const uint32_t* Kh_g = g_Kph + (size_t)bh * SS * DKP;
    const uint32_t* Kl_g = g_Kpl + (size_t)bh * SS * DKP;
    const uint32_t* Vh_g = g_Vth + (size_t)bh * DKK * (SS/2);
    const uint32_t* Vl_g = g_Vtl + (size_t)bh * DKK * (SS/2);

    // load Q tile (64 rows x 32 pairs) into planes 0/1
    #pragma unroll
    for (int r = 0; r < 4; r++) {
        int c = tid + r * 128;
        int row = c >> 3, seg = c & 7;
        CP_ASYNC16(sb + ((0*APL + row*PLW + seg*4) << 2), Qh_g + (size_t)(i0+row)*DKP + seg*4);
        CP_ASYNC16(sb + ((1*APL + row*PLW + seg*4) << 2), Ql_g + (size_t)(i0+row)*DKP + seg*4);
    }
    CP_COMMIT();

    float mrow[2] = {-1e30f, -1e30f};
    float lsum[2] = {0.f, 0.f};
    float oacc[8][4] = {};

    for (int j = 0; j <= qi; j++) {
        const int j0 = j * 64;
        // load K (planes 2/3) and V^T (planes 4/5)
        #pragma unroll
        for (int r = 0; r < 4; r++) {
            int c = tid + r * 128;
            int row = c >> 3, seg = c & 7;
            CP_ASYNC16(sb + ((2*APL + row*PLW + seg*4) << 2), Kh_g + (size_t)(j0+row)*DKP + seg*4);
            CP_ASYNC16(sb + ((3*APL + row*PLW + seg*4) << 2), Kl_g + (size_t)(j0+row)*DKP + seg*4);
            CP_ASYNC16(sb + ((4*APL + row*PLW + seg*4) << 2), Vh_g + (size_t)row*(SS/2) + j0/2 + seg*4);
            CP_ASYNC16(sb + ((5*APL + row*PLW + seg*4) << 2), Vl_g + (size_t)row*(SS/2) + j0/2 + seg*4);
        }
        CP_COMMIT();
        CP_WAIT0();
        __syncthreads();

        // ---- QK^T (bf16x3): warp computes 16 rows x 64 cols ----
        float acc[8][4] = {};
        {
            const uint32_t* Qh_s = smw + 0*APL;
            const uint32_t* Ql_s = smw + 1*APL;
            const uint32_t* Kh_s = smw + 2*APL;
            const uint32_t* Kl_s = smw + 3*APL;
            #pragma unroll
            for (int kf = 0; kf < 4; kf++) {
                const int kb = kf * 8;
                uint32_t ah[4], al[4];
                ah[0] = Qh_s[(mb+g  )*PLW + kb+tg  ]; al[0] = Ql_s[(mb+g  )*PLW + kb+tg  ];
                ah[1] = Qh_s[(mb+g+8)*PLW + kb+tg  ]; al[1] = Ql_s[(mb+g+8)*PLW + kb+tg  ];
                ah[2] = Qh_s[(mb+g  )*PLW + kb+tg+4]; al[2] = Ql_s[(mb+g  )*PLW + kb+tg+4];
                ah[3] = Qh_s[(mb+g+8)*PLW + kb+tg+4]; al[3] = Ql_s[(mb+g+8)*PLW + kb+tg+4];
                #pragma unroll
                for (int nf = 0; nf < 8; nf++) {
                    int nb = nf * 8 + g;
                    uint32_t bh2[2], bl2[2];
                    bh2[0] = Kh_s[nb*PLW + kb+tg]; bh2[1] = Kh_s[nb*PLW + kb+tg+4];
                    bl2[0] = Kl_s[nb*PLW + kb+tg]; bl2[1] = Kl_s[nb*PLW + kb+tg+4];
                    mma_bf16(acc[nf], ah, bh2);
                    mma_bf16(acc[nf], ah, bl2);
                    mma_bf16(acc[nf], al, bh2);
                }
            }
        }

        // ---- mask + online softmax (full row inside this warp) ----
        const bool diag = (j == qi);
        #pragma unroll
        for (int half = 0; half < 2; half++) {
            const int r = i0 + mb + g + half * 8;
            float mx = -1e30f;
            #pragma unroll
            for (int nf = 0; nf < 8; nf++) {
                #pragma unroll
                for (int e = 0; e < 2; e++) {
                    float sv = acc[nf][half*2+e];
                    if (diag && (j0 + nf*8 + 2*tg + e) > r) {
                        sv = -1e30f;
                        acc[nf][half*2+e] = sv;
                    }
                    mx = fmaxf(mx, sv);
                }
            }
            mx = fmaxf(mx, __shfl_xor_sync(0xffffffffu, mx, 1));
            mx = fmaxf(mx, __shfl_xor_sync(0xffffffffu, mx, 2));
            float mnew = fmaxf(mrow[half], mx);
            float corr = __expf(mrow[half] - mnew);
            mrow[half] = mnew;
            float rs = 0.f;
            #pragma unroll
            for (int nf = 0; nf < 8; nf++) {
                #pragma unroll
                for (int e = 0; e < 2; e++) {
                    float p = __expf(acc[nf][half*2+e] - mnew);
                    acc[nf][half*2+e] = p;
                    rs += p;
                }
            }
            rs += __shfl_xor_sync(0xffffffffu, rs, 1);
            rs += __shfl_xor_sync(0xffffffffu, rs, 2);
            lsum[half] = lsum[half] * corr + rs;
            #pragma unroll
            for (int nf = 0; nf < 8; nf++)
                #pragma unroll
                for (int e = 0; e < 2; e++)
                    oacc[nf][half*2+e] *= corr;
        }

        // ---- split P to bf16 pairs in smem (planes 6/7) ----
        #pragma unroll
        for (int half = 0; half < 2; half++) {
            int rowi = mb + g + half * 8;
            #pragma unroll
            for (int nf = 0; nf < 8; nf++) {
                uint32_t hi, lo;
                split2(acc[nf][half*2], acc[nf][half*2+1], hi, lo);
                int idx = rowi * PLW + nf * 4 + tg;
                smw[6*APL + idx] = hi;
                smw[7*APL + idx] = lo;
            }
        }
        __syncwarp();   // P rows are private to this warp; no cross-warp P reads

        // ---- P @ V (bf16x3): A = P(16x64 rows of this warp), B = V^T(64 dk x 64 t) ----
        {
            const uint32_t* Ph_s = smw + 6*APL;
            const uint32_t* Pl_s = smw + 7*APL;
            const uint32_t* Vh_s = smw + 4*APL;
            const uint32_t* Vl_s = smw + 5*APL;
            #pragma unroll
            for (int kf = 0; kf < 4; kf++) {
                const int kb = kf * 8;
                uint32_t ph[4], pl[4];
                ph[0] = Ph_s[(mb+g  )*PLW + kb+tg  ]; pl[0] = Pl_s[(mb+g  )*PLW + kb+tg  ];
                ph[1] = Ph_s[(mb+g+8)*PLW + kb+tg  ]; pl[1] = Pl_s[(mb+g+8)*PLW + kb+tg  ];
                ph[2] = Ph_s[(mb+g  )*PLW + kb+tg+4]; pl[2] = Pl_s[(mb+g  )*PLW + kb+tg+4];
                ph[3] = Ph_s[(mb+g+8)*PLW + kb+tg+4]; pl[3] = Pl_s[(mb+g+8)*PLW + kb+tg+4];
                #pragma unroll
                for (int nf = 0; nf < 8; nf++) {
                    int nb = nf * 8 + g;
                    uint32_t vbh[2], vbl[2];
                    vbh[0] = Vh_s[nb*PLW + kb+tg]; vbh[1] = Vh_s[nb*PLW + kb+tg+4];
                    vbl[0] = Vl_s[nb*PLW + kb+tg]; vbl[1] = Vl_s[nb*PLW + kb+tg+4];
                    mma_bf16(oacc[nf], ph, vbh);
                    mma_bf16(oacc[nf], ph, vbl);
                    mma_bf16(oacc[nf], pl, vbh);
                }
            }
        }
        __syncthreads();   // done reading K/V planes before next-iter overwrite
    }

    // ---- epilogue: normalize, split, write Ctx pairs ----
    const int b_ = bh / HH, h = bh % HH;
    const float inv0 = 1.f / lsum[0];
    const float inv1 = 1.f / lsum[1];
    const int r0 = i0 + mb + g;
    #pragma unroll
    for (int nf = 0; nf < 8; nf++) {
        int pidx = h * 32 + nf * 4 + tg;   // column pair index within 1024-wide Ctx
        {
            size_t o = ((size_t)(b_ * SS + r0)) * KP + pidx;
            uint32_t hi, lo;
            split2(oacc[nf][0] * inv0, oacc[nf][1] * inv0, hi, lo);
            g_Ch[o] = hi; g_Cl[o] = lo;
        }
        {
            size_t o = ((size_t)(b_ * SS + r0 + 8)) * KP + pidx;
            uint32_t hi, lo;
            split2(oacc[nf][2] * inv1, oacc[nf][3] * inv1, hi, lo);
            g_Ch[o] = hi; g_Cl[o] = lo;
        }
    }
}

// ---------------------------------------------------------------------------
extern "C" void kernel_launch(void* const* d_in, const int* in_sizes, int n_in,
                              void* d_out, int out_size)
{
    const float* q  = (const float*)d_in[0];
    const float* k  = (const float*)d_in[1];
    const float* v  = (const float*)d_in[2];
    const float* Wq = (const float*)d_in[3];
    const float* Wk = (const float*)d_in[4];
    const float* Wv = (const float*)d_in[5];
    const float* Wo = (const float*)d_in[6];
    const float* bo = (const float*)d_in[7];
    float* out = (float*)d_out;

    cudaFuncSetAttribute(gemm_proj_tc, cudaFuncAttributeMaxDynamicSharedMemorySize, SMEM_GEMM_BYTES);
    cudaFuncSetAttribute(gemm_out_tc,  cudaFuncAttributeMaxDynamicSharedMemorySize, SMEM_GEMM_BYTES);
    cudaFuncSetAttribute(attn_tc,      cudaFuncAttributeMaxDynamicSharedMemorySize, SMEM_ATTN_BYTES);

    convert_x<<<3 * MM, 256>>>(q, k, v);
    convert_w<<<3 * HH * KP * 16 / 256, 256>>>(Wq, Wk, Wv);
    convert_wo<<<DD, 256>>>(Wo);

    gemm_proj_tc<<<dim3(MM / 128, DD / 128, 3), 256, SMEM_GEMM_BYTES>>>();

    convert_vt<<<dim3(SS / 32, BHH), 256>>>();

    attn_tc<<<dim3(32, BHH), 128, SMEM_ATTN_BYTES>>>();

    gemm_out_tc<<<dim3(MM / 128, DD / 128), 256, SMEM_GEMM_BYTES>>>(bo, out);
}